// round 5
// baseline (speedup 1.0000x reference)
#include <cuda_runtime.h>

#define PVOL   29791          // 31^3
#define MROWS  119164         // 4 * 31^3
#define D1     512
#define KK     128
#define BM     128
#define BN     128

// XOR swizzle on the m index (16B granular): conflict-free stride-8 LDS.128
#define SW(m) ((m) ^ ((((m) >> 5) & 1) << 2))

__device__ __forceinline__ void unpack2(unsigned long long v, float& lo, float& hi) {
    asm("mov.b64 {%0, %1}, %2;" : "=f"(lo), "=f"(hi) : "l"(v));
}
__device__ __forceinline__ void ffma2(unsigned long long& acc,
                                      unsigned long long a, unsigned long long b) {
    asm("fma.rn.f32x2 %0, %1, %2, %0;" : "+l"(acc) : "l"(a), "l"(b));
}

__global__ __launch_bounds__(256, 1)
void gk_kernel(const float* __restrict__ x, const float* __restrict__ w,
               float* __restrict__ out) {
    extern __shared__ float sm[];
    float* sA   = sm;                       // [KK][128]  patches, swizzled in m
    float* sB   = sm + KK * 128;            // [KK][256]  w DUPLICATED {b,b} pairs
    float* ysqp = sm + KK * 128 + KK * 256; // [2][128] partial ||y||^2
    float* wsqp = ysqp + 256;               // [2][128] partial ||w||^2
    float* st   = sB;                       // stage reuses sB after GEMM

    const int tid  = threadIdx.x;
    const int row0 = blockIdx.x * BM;
    const int col0 = blockIdx.y * BN;

    // ---------------- gather A + ||y||^2 partials ---------------------------
    {
        const int m   = tid & 127;
        const int kw  = tid >> 7;            // innermost patch bit
        const int row = row0 + m;
        const int ms  = SW(m);
        float s = 0.0f;
        if (row < MROWS) {
            const int n   = row / PVOL;
            const int p   = row - n * PVOL;
            const int d   = p / 961;
            const int rem = p - d * 961;
            const int h   = rem / 31;
            const int wx  = rem - h * 31;
            const long base = (long)n * 524288 + d * 1024 + h * 32 + wx + kw;
            #pragma unroll 8
            for (int it = 0; it < 64; ++it) {
                const int c  = it >> 2;
                const int kd = (it >> 1) & 1;
                const int kh = it & 1;
                const float v = x[base + (long)c * 32768 + kd * 1024 + kh * 32];
                sA[(it * 2 + kw) * 128 + ms] = v;
                s = fmaf(v, v, s);
            }
        } else {
            #pragma unroll 8
            for (int it = 0; it < 64; ++it)
                sA[(it * 2 + kw) * 128 + ms] = 0.0f;
        }
        ysqp[kw * 128 + m] = s;
    }

    // ---------------- fill B duplicated {b,b} + ||w||^2 partials ------------
    {
        const int nn   = tid & 127;
        const int half = tid >> 7;
        float s = 0.0f;
        #pragma unroll
        for (int it = 0; it < 16; ++it) {
            const int k4 = half + it * 2;      // quad of k values
            const float4 v = *(const float4*)&w[(long)(col0 + nn) * KK + k4 * 4];
            *(float2*)&sB[(k4 * 4 + 0) * 256 + 2 * nn] = make_float2(v.x, v.x);
            *(float2*)&sB[(k4 * 4 + 1) * 256 + 2 * nn] = make_float2(v.y, v.y);
            *(float2*)&sB[(k4 * 4 + 2) * 256 + 2 * nn] = make_float2(v.z, v.z);
            *(float2*)&sB[(k4 * 4 + 3) * 256 + 2 * nn] = make_float2(v.w, v.w);
            s = fmaf(v.x, v.x, s);
            s = fmaf(v.y, v.y, s);
            s = fmaf(v.z, v.z, s);
            s = fmaf(v.w, v.w, s);
        }
        wsqp[half * 128 + nn] = s;
    }
    __syncthreads();

    // ---------------- GEMM: 8x8 micro-tile, zero-pack FFMA2 -----------------
    const int tx = tid & 15;
    const int ty = tid >> 4;
    const int tm = tx * 8;
    const int tn = ty * 8;

    unsigned long long acc[4][8];
    #pragma unroll
    for (int i = 0; i < 4; ++i)
        #pragma unroll
        for (int j = 0; j < 8; ++j) acc[i][j] = 0ull;

    const int tms0 = SW(tm);
    const int tms1 = SW(tm + 4);
    const float* pB = sB + 2 * tn;

    #pragma unroll 2
    for (int k = 0; k < KK; ++k) {
        // A: two LDS.128, each read as 2 pre-packed f32x2 — no MOVs
        const ulonglong2 a01 = *(const ulonglong2*)&sA[k * 128 + tms0];
        const ulonglong2 a23 = *(const ulonglong2*)&sA[k * 128 + tms1];
        unsigned long long A[4] = {a01.x, a01.y, a23.x, a23.y};

        // B: eight LDS.64 of duplicated {b,b} pairs — no MOVs, broadcast lanes
        unsigned long long B[8];
        #pragma unroll
        for (int j = 0; j < 8; ++j)
            B[j] = *(const unsigned long long*)&pB[k * 256 + 2 * j];

        #pragma unroll
        for (int i = 0; i < 4; ++i)
            #pragma unroll
            for (int j = 0; j < 8; ++j)
                ffma2(acc[i][j], A[i], B[j]);
    }

    float ys[8], ws[8];
    #pragma unroll
    for (int i = 0; i < 8; ++i) ys[i] = ysqp[tm + i] + ysqp[128 + tm + i];
    #pragma unroll
    for (int j = 0; j < 8; ++j) ws[j] = wsqp[tn + j] + wsqp[128 + tn + j];

    __syncthreads();                  // sB reads done; reuse as stage

    // ---------------- epilogue: exp -> swizzled stage ------------------------
    #pragma unroll
    for (int i = 0; i < 4; ++i) {
        #pragma unroll
        for (int j = 0; j < 8; ++j) {
            float v0, v1;
            unpack2(acc[i][j], v0, v1);
            const float e0 = __expf(fmaf(2.0f, v0, -(ys[2 * i]     + ws[j])));
            const float e1 = __expf(fmaf(2.0f, v1, -(ys[2 * i + 1] + ws[j])));
            *(float2*)&st[(tn + j) * 128 + SW(tm + 2 * i)] = make_float2(e0, e1);
        }
    }
    __syncthreads();

    // ---------------- coalesced global stores --------------------------------
    #pragma unroll 4
    for (int l = 0; l < 64; ++l) {
        const int e   = tid + l * 256;
        const int col = e >> 7;
        const int m   = e & 127;
        const int row = row0 + m;
        if (row < MROWS) {
            const int n = row / PVOL;
            const int p = row - n * PVOL;
            out[(long)(n * D1 + col0 + col) * PVOL + p] = st[col * 128 + SW(m)];
        }
    }
}

extern "C" void kernel_launch(void* const* d_in, const int* in_sizes, int n_in,
                              void* d_out, int out_size) {
    const float* x = (const float*)d_in[0];
    const float* w = (const float*)d_in[1];
    float* out = (float*)d_out;

    const int smem_bytes = (KK * 128 + KK * 256 + 512) * (int)sizeof(float); // 198,656
    cudaFuncSetAttribute(gk_kernel, cudaFuncAttributeMaxDynamicSharedMemorySize,
                         smem_bytes);

    dim3 grid((MROWS + BM - 1) / BM, D1 / BN);  // (931, 4)
    gk_kernel<<<grid, 256, smem_bytes>>>(x, w, out);
}

// round 6
// speedup vs baseline: 1.1065x; 1.1065x over previous
#include <cuda_runtime.h>

#define PVOL   29791          // 31^3
#define MROWS  119164         // 4 * 31^3
#define D1     512
#define KK     128
#define BM     128
#define BN     256
#define NT     512

// XOR swizzle on the m index (16B granular): conflict-free stride-8 LDS.128
#define SW(m) ((m) ^ ((((m) >> 5) & 1) << 2))

__device__ __forceinline__ unsigned long long pack2(float lo, float hi) {
    unsigned long long r;
    asm("mov.b64 %0, {%1, %2};" : "=l"(r) : "f"(lo), "f"(hi));
    return r;
}
__device__ __forceinline__ void unpack2(unsigned long long v, float& lo, float& hi) {
    asm("mov.b64 {%0, %1}, %2;" : "=f"(lo), "=f"(hi) : "l"(v));
}
__device__ __forceinline__ void ffma2(unsigned long long& acc,
                                      unsigned long long a, unsigned long long b) {
    asm("fma.rn.f32x2 %0, %1, %2, %0;" : "+l"(acc) : "l"(a), "l"(b));
}

__global__ __launch_bounds__(NT, 1)
void gk_kernel(const float* __restrict__ x, const float* __restrict__ w,
               float* __restrict__ out) {
    extern __shared__ float sm[];
    float* sA   = sm;                        // [KK][128]  patches, swizzled in m
    float* sB   = sm + KK * 128;             // [KK][256]  w, k-major
    float* ysqp = sm + KK * 128 + KK * 256;  // [4][128] partial ||y||^2
    float* wsqp = ysqp + 512;                // [2][256] partial ||w||^2
    float* st   = sB;                        // [BN][128] stage reuses sB

    const int tid  = threadIdx.x;
    const int row0 = blockIdx.x * BM;
    const int col0 = blockIdx.y * BN;

    // ---------------- gather A + ||y||^2 partials ---------------------------
    {
        const int m   = tid & 127;
        const int khw = tid >> 7;             // 0..3 = (kh,kw)
        const int row = row0 + m;
        const int ms  = SW(m);
        float s = 0.0f;
        if (row < MROWS) {
            const int n   = row / PVOL;
            const int p   = row - n * PVOL;
            const int d   = p / 961;
            const int rem = p - d * 961;
            const int h   = rem / 31;
            const int wx  = rem - h * 31;
            const int kh  = khw >> 1;
            const int kw  = khw & 1;
            const long base = (long)n * 524288 + d * 1024 + h * 32 + wx
                              + kh * 32 + kw;
            #pragma unroll 8
            for (int it = 0; it < 32; ++it) {
                const int c  = it >> 1;
                const int kd = it & 1;
                const float v = x[base + (long)c * 32768 + kd * 1024];
                sA[(it * 4 + khw) * 128 + ms] = v;   // k = c*8+kd*4+kh*2+kw
                s = fmaf(v, v, s);
            }
        } else {
            #pragma unroll 8
            for (int it = 0; it < 32; ++it)
                sA[(it * 4 + khw) * 128 + ms] = 0.0f;
        }
        ysqp[khw * 128 + m] = s;
    }

    // ---------------- fill B + ||w||^2 partials -----------------------------
    {
        const int nn   = tid & 255;
        const int half = tid >> 8;            // 0..1
        float s = 0.0f;
        #pragma unroll
        for (int it = 0; it < 16; ++it) {
            const int k4 = half + it * 2;     // quad of k values
            const float4 v = *(const float4*)&w[(long)(col0 + nn) * KK + k4 * 4];
            sB[(k4 * 4 + 0) * 256 + nn] = v.x;
            sB[(k4 * 4 + 1) * 256 + nn] = v.y;
            sB[(k4 * 4 + 2) * 256 + nn] = v.z;
            sB[(k4 * 4 + 3) * 256 + nn] = v.w;
            s = fmaf(v.x, v.x, s);
            s = fmaf(v.y, v.y, s);
            s = fmaf(v.z, v.z, s);
            s = fmaf(v.w, v.w, s);
        }
        wsqp[half * 256 + nn] = s;
    }
    __syncthreads();

    // ---------------- GEMM: 8x8 micro-tile, FFMA2 ---------------------------
    const int tx = tid & 15;
    const int ty = tid >> 4;      // 0..31
    const int tm = tx * 8;
    const int tn = ty * 8;

    unsigned long long acc[4][8];
    #pragma unroll
    for (int i = 0; i < 4; ++i)
        #pragma unroll
        for (int j = 0; j < 8; ++j) acc[i][j] = 0ull;

    const int tms0 = SW(tm);
    const int tms1 = SW(tm + 4);

    #pragma unroll 4
    for (int k = 0; k < KK; ++k) {
        const ulonglong2 a01 = *(const ulonglong2*)&sA[k * 128 + tms0];
        const ulonglong2 a23 = *(const ulonglong2*)&sA[k * 128 + tms1];
        unsigned long long A[4] = {a01.x, a01.y, a23.x, a23.y};

        const float4 b0 = *(const float4*)&sB[k * 256 + tn];
        const float4 b1 = *(const float4*)&sB[k * 256 + tn + 4];
        unsigned long long B[8];
        B[0] = pack2(b0.x, b0.x);
        B[1] = pack2(b0.y, b0.y);
        B[2] = pack2(b0.z, b0.z);
        B[3] = pack2(b0.w, b0.w);
        B[4] = pack2(b1.x, b1.x);
        B[5] = pack2(b1.y, b1.y);
        B[6] = pack2(b1.z, b1.z);
        B[7] = pack2(b1.w, b1.w);

        #pragma unroll
        for (int i = 0; i < 4; ++i)
            #pragma unroll
            for (int j = 0; j < 8; ++j)
                ffma2(acc[i][j], A[i], B[j]);
    }

    float ys[8], ws[8];
    #pragma unroll
    for (int i = 0; i < 8; ++i)
        ys[i] = (ysqp[tm + i] + ysqp[128 + tm + i])
              + (ysqp[256 + tm + i] + ysqp[384 + tm + i]);
    #pragma unroll
    for (int j = 0; j < 8; ++j)
        ws[j] = wsqp[tn + j] + wsqp[256 + tn + j];

    __syncthreads();                  // sB reads done; reuse as stage

    // ---------------- epilogue: exp -> swizzled stage ------------------------
    #pragma unroll
    for (int i = 0; i < 4; ++i) {
        #pragma unroll
        for (int j = 0; j < 8; ++j) {
            float v0, v1;
            unpack2(acc[i][j], v0, v1);
            const float e0 = __expf(fmaf(2.0f, v0, -(ys[2 * i]     + ws[j])));
            const float e1 = __expf(fmaf(2.0f, v1, -(ys[2 * i + 1] + ws[j])));
            *(float2*)&st[(tn + j) * 128 + SW(tm + 2 * i)] = make_float2(e0, e1);
        }
    }
    __syncthreads();

    // ---------------- coalesced global stores --------------------------------
    #pragma unroll 4
    for (int l = 0; l < 64; ++l) {
        const int e   = tid + l * NT;
        const int col = e >> 7;           // 0..255
        const int m   = e & 127;
        const int row = row0 + m;
        if (row < MROWS) {
            const int n = row / PVOL;
            const int p = row - n * PVOL;
            out[(long)(n * D1 + col0 + col) * PVOL + p] = st[col * 128 + SW(m)];
        }
    }
}

extern "C" void kernel_launch(void* const* d_in, const int* in_sizes, int n_in,
                              void* d_out, int out_size) {
    const float* x = (const float*)d_in[0];
    const float* w = (const float*)d_in[1];
    float* out = (float*)d_out;

    const int smem_bytes = (KK * 128 + KK * 256 + 1024) * (int)sizeof(float); // 200,704
    cudaFuncSetAttribute(gk_kernel, cudaFuncAttributeMaxDynamicSharedMemorySize,
                         smem_bytes);

    dim3 grid((MROWS + BM - 1) / BM, D1 / BN);  // (931, 2)
    gk_kernel<<<grid, NT, smem_bytes>>>(x, w, out);
}